// round 1
// baseline (speedup 1.0000x reference)
#include <cuda_runtime.h>
#include <math.h>

#define NB   8
#define NN   256
#define NH   4
#define HD   64
#define FIN  256
#define ALPHA 0.2f

// Scratch (allocation-free rule: __device__ globals)
__device__ float g_Wh[NB*NH*NN*HD];
__device__ float g_si[NB*NH*NN*HD];
__device__ float g_sj[NB*NH*NN*HD];
__device__ float g_ei[NB*NH*NN*HD];
__device__ float g_ej[NB*NH*NN*HD];
__device__ float g_concat[NB*NN*FIN];

// ---------------------------------------------------------------------------
// Kernel 1: per (b, 16-row tile): Wh = h@W, ei = h@We1[:IN]+be1, ej = h@We1[IN:],
// then si = Wh@Wa + ba1, sj = Wh@Wb.  Layout of all outputs: [b][head][n][d].
// ---------------------------------------------------------------------------
__global__ __launch_bounds__(256) void k1_proj(
    const float* __restrict__ hin, const float* __restrict__ W,
    const float* __restrict__ We1, const float* __restrict__ be1,
    const float* __restrict__ Wa1, const float* __restrict__ ba1)
{
    const int NT = 16;
    int b  = blockIdx.x / (NN / NT);
    int n0 = (blockIdx.x % (NN / NT)) * NT;
    int tid = threadIdx.x;
    int head = tid >> 6, d = tid & 63;

    __shared__ float hs[NT][FIN];
    __shared__ float whs[NT][FIN];

    for (int nn = 0; nn < NT; ++nn)
        hs[nn][tid] = hin[((size_t)(b*NN + n0 + nn))*FIN + tid];
    __syncthreads();

    float accW[NT], accE1[NT], accE2[NT];
#pragma unroll
    for (int nn = 0; nn < NT; ++nn) { accW[nn]=0.f; accE1[nn]=0.f; accE2[nn]=0.f; }

    for (int f = 0; f < FIN; ++f) {
        float wv = W  [((size_t)head*FIN + f)*HD + d];
        float w1 = We1[((size_t)head*2*FIN + f)*HD + d];
        float w2 = We1[((size_t)head*2*FIN + FIN + f)*HD + d];
#pragma unroll
        for (int nn = 0; nn < NT; ++nn) {
            float hv = hs[nn][f];
            accW[nn]  = fmaf(hv, wv, accW[nn]);
            accE1[nn] = fmaf(hv, w1, accE1[nn]);
            accE2[nn] = fmaf(hv, w2, accE2[nn]);
        }
    }

    float bei = be1[head*HD + d];
    for (int nn = 0; nn < NT; ++nn) {
        size_t base = ((size_t)(b*NH + head)*NN + (n0 + nn))*HD + d;
        g_Wh[base] = accW[nn];
        g_ei[base] = accE1[nn] + bei;
        g_ej[base] = accE2[nn];
        whs[nn][head*HD + d] = accW[nn];
    }
    __syncthreads();

    float accSi[NT], accSj[NT];
#pragma unroll
    for (int nn = 0; nn < NT; ++nn) { accSi[nn]=0.f; accSj[nn]=0.f; }

    for (int d2 = 0; d2 < HD; ++d2) {
        float wa = Wa1[((size_t)head*3*HD + d2)*HD + d];
        float wb = Wa1[((size_t)head*3*HD + HD + d2)*HD + d];
#pragma unroll
        for (int nn = 0; nn < NT; ++nn) {
            float wh = whs[nn][head*HD + d2];
            accSi[nn] = fmaf(wh, wa, accSi[nn]);
            accSj[nn] = fmaf(wh, wb, accSj[nn]);
        }
    }
    float bsi = ba1[head*HD + d];
    for (int nn = 0; nn < NT; ++nn) {
        size_t base = ((size_t)(b*NH + head)*NN + (n0 + nn))*HD + d;
        g_si[base] = accSi[nn] + bsi;
        g_sj[base] = accSj[nn];
    }
}

// ---------------------------------------------------------------------------
// Kernel 2: one block per (b, head, i).  256 threads = 64 j-values x 4 d-groups.
// Computes e[i, j] for all j (edge@We GEMM fused with leaky-relus and wa2 dot),
// masked softmax over j, hp = attn @ Wh, per-head layernorm -> g_concat.
// ---------------------------------------------------------------------------
__global__ __launch_bounds__(256) void k2_attn(
    const float* __restrict__ Wa1, const float* __restrict__ wa2,
    const float* __restrict__ ba2, const int* __restrict__ adj,
    const float* __restrict__ ln_g, const float* __restrict__ ln_b)
{
    int bx   = blockIdx.x;
    int i    = bx & (NN - 1);
    int head = (bx >> 8) & (NH - 1);
    int b    = bx >> 10;
    int tid  = threadIdx.x;
    int jj   = tid >> 2;     // 0..63  (j within tile)
    int dg   = tid & 3;      // 0..3   (d-group of 16)
    int db   = dg * 16;

    __shared__ float ej_s[64][65];   // padded: stride 65 -> conflict-free column reads
    __shared__ float We_s[64][64];   // [k][d], rows 16B-aligned for float4 broadcast
    __shared__ float ei_s[64];
    __shared__ float si_s[64];
    __shared__ float wa2_s[64];
    __shared__ float e_s[256];
    __shared__ float hp_s[4][64];
    __shared__ float red_s[16];

    size_t bh = (size_t)(b*NH + head);
    const float* ej_base = g_ej + bh*NN*HD;
    const float* sj_base = g_sj + bh*NN*HD;
    const float* wh_base = g_Wh + bh*NN*HD;

    for (int t = tid; t < 64*64; t += 256)
        We_s[t >> 6][t & 63] = Wa1[((size_t)head*3*HD + 2*HD + (t >> 6))*HD + (t & 63)];
    if (tid < 64) {
        ei_s[tid]  = g_ei[(bh*NN + i)*HD + tid];
        si_s[tid]  = g_si[(bh*NN + i)*HD + tid];
        wa2_s[tid] = wa2[head*HD + tid];
    }
    float ba2v = ba2[head];

    for (int jt = 0; jt < 4; ++jt) {
        __syncthreads();
        int j0 = jt * 64;
        for (int t = tid; t < 64*64; t += 256)
            ej_s[t >> 6][t & 63] = ej_base[(size_t)(j0 + (t >> 6))*HD + (t & 63)];
        __syncthreads();

        float acc[16];
#pragma unroll
        for (int q = 0; q < 16; ++q) acc[q] = 0.f;

#pragma unroll 4
        for (int k = 0; k < 64; ++k) {
            float x  = ei_s[k] + ej_s[jj][k];
            float ev = fmaxf(x, ALPHA * x);              // leaky_relu
            const float4* wp = reinterpret_cast<const float4*>(&We_s[k][db]);
            float4 w0 = wp[0], w1 = wp[1], w2 = wp[2], w3 = wp[3];
            acc[0]  = fmaf(ev, w0.x, acc[0]);  acc[1]  = fmaf(ev, w0.y, acc[1]);
            acc[2]  = fmaf(ev, w0.z, acc[2]);  acc[3]  = fmaf(ev, w0.w, acc[3]);
            acc[4]  = fmaf(ev, w1.x, acc[4]);  acc[5]  = fmaf(ev, w1.y, acc[5]);
            acc[6]  = fmaf(ev, w1.z, acc[6]);  acc[7]  = fmaf(ev, w1.w, acc[7]);
            acc[8]  = fmaf(ev, w2.x, acc[8]);  acc[9]  = fmaf(ev, w2.y, acc[9]);
            acc[10] = fmaf(ev, w2.z, acc[10]); acc[11] = fmaf(ev, w2.w, acc[11]);
            acc[12] = fmaf(ev, w3.x, acc[12]); acc[13] = fmaf(ev, w3.y, acc[13]);
            acc[14] = fmaf(ev, w3.z, acc[14]); acc[15] = fmaf(ev, w3.w, acc[15]);
        }

        const float* sjrow = sj_base + (size_t)(j0 + jj)*HD + db;
        float pe = 0.f;
#pragma unroll
        for (int dd = 0; dd < 16; ++dd) {
            float t2  = si_s[db + dd] + sjrow[dd] + acc[dd];
            float hdn = fmaxf(t2, ALPHA * t2);           // leaky_relu
            pe = fmaf(hdn, wa2_s[db + dd], pe);
        }
        pe += __shfl_xor_sync(0xffffffffu, pe, 1);
        pe += __shfl_xor_sync(0xffffffffu, pe, 2);
        if (dg == 0) {
            int j = j0 + jj;
            int a = adj[((size_t)b*NN + i)*NN + j];
            e_s[j] = (a == 0) ? -1e9f : (pe + ba2v);
        }
    }
    __syncthreads();

    // ---- masked softmax over j = 0..255 ----
    float v  = e_s[tid];
    float mx = v;
#pragma unroll
    for (int o = 16; o; o >>= 1) mx = fmaxf(mx, __shfl_xor_sync(0xffffffffu, mx, o));
    if ((tid & 31) == 0) red_s[tid >> 5] = mx;
    __syncthreads();
    if (tid == 0) {
        float m = red_s[0];
        for (int w = 1; w < 8; ++w) m = fmaxf(m, red_s[w]);
        red_s[0] = m;
    }
    __syncthreads();
    float p  = expf(v - red_s[0]);
    float sm = p;
#pragma unroll
    for (int o = 16; o; o >>= 1) sm += __shfl_xor_sync(0xffffffffu, sm, o);
    if ((tid & 31) == 0) red_s[8 + (tid >> 5)] = sm;
    __syncthreads();
    if (tid == 0) {
        float s = 0.f;
        for (int w = 0; w < 8; ++w) s += red_s[8 + w];
        red_s[8] = 1.0f / s;
    }
    __syncthreads();
    e_s[tid] = p * red_s[8];          // attn
    __syncthreads();

    // ---- hp[d] = sum_j attn[j] * Wh[j][d] ----
    int d = tid & 63, q = tid >> 6;
    float a2 = 0.f;
    const float* whq = wh_base + (size_t)q*64*HD + d;
#pragma unroll 4
    for (int j = 0; j < 64; ++j)
        a2 = fmaf(e_s[q*64 + j], whq[(size_t)j*HD], a2);
    hp_s[q][d] = a2;
    __syncthreads();
    if (tid < 64)
        e_s[tid] = hp_s[0][tid] + hp_s[1][tid] + hp_s[2][tid] + hp_s[3][tid];
    __syncthreads();

    // ---- per-head layernorm over 64 dims ----
    if (tid < 32) {
        float x0 = e_s[tid], x1 = e_s[tid + 32];
        float s1 = x0 + x1;
        float s2 = x0*x0 + x1*x1;
#pragma unroll
        for (int o = 16; o; o >>= 1) {
            s1 += __shfl_xor_sync(0xffffffffu, s1, o);
            s2 += __shfl_xor_sync(0xffffffffu, s2, o);
        }
        if (tid == 0) { red_s[0] = s1 * (1.0f/64.0f); red_s[1] = s2 * (1.0f/64.0f); }
    }
    __syncthreads();
    if (tid < 64) {
        float m   = red_s[0];
        float var = red_s[1] - m*m;
        float r   = rsqrtf(var + 1e-5f);
        float y   = (e_s[tid] - m) * r * ln_g[head*HD + tid] + ln_b[head*HD + tid];
        g_concat[((size_t)b*NN + i)*FIN + head*HD + tid] = y;
    }
}

// ---------------------------------------------------------------------------
// Kernel 3: out = layernorm(concat @ Wo + bo + h), blocks of 8 rows.
// ---------------------------------------------------------------------------
__global__ __launch_bounds__(256) void k3_out(
    const float* __restrict__ hin, const float* __restrict__ Wo,
    const float* __restrict__ bo,  const float* __restrict__ g2,
    const float* __restrict__ b2,  float* __restrict__ out)
{
    const int NT = 8;
    int b  = blockIdx.x / (NN / NT);
    int n0 = (blockIdx.x % (NN / NT)) * NT;
    int tid = threadIdx.x;

    __shared__ float cs[NT][FIN];
    __shared__ float hs2[NT][FIN];

    for (int nn = 0; nn < NT; ++nn) {
        cs[nn][tid]  = g_concat[((size_t)b*NN + n0 + nn)*FIN + tid];
        hs2[nn][tid] = hin     [((size_t)b*NN + n0 + nn)*FIN + tid];
    }
    __syncthreads();

    float acc[NT];
    float bv = bo[tid];
#pragma unroll
    for (int nn = 0; nn < NT; ++nn) acc[nn] = bv;

    for (int f = 0; f < FIN; ++f) {
        float w = Wo[(size_t)f*FIN + tid];
#pragma unroll
        for (int nn = 0; nn < NT; ++nn)
            acc[nn] = fmaf(cs[nn][f], w, acc[nn]);
    }
    __syncthreads();
    for (int nn = 0; nn < NT; ++nn)
        cs[nn][tid] = acc[nn] + hs2[nn][tid];
    __syncthreads();

    // layernorm: one warp per row
    int wr = tid >> 5, lane = tid & 31;
    float s1 = 0.f, s2 = 0.f;
    for (int o = lane; o < FIN; o += 32) {
        float x = cs[wr][o]; s1 += x; s2 += x*x;
    }
#pragma unroll
    for (int o = 16; o; o >>= 1) {
        s1 += __shfl_xor_sync(0xffffffffu, s1, o);
        s2 += __shfl_xor_sync(0xffffffffu, s2, o);
    }
    float m   = s1 * (1.0f/256.0f);
    float var = s2 * (1.0f/256.0f) - m*m;
    float r   = rsqrtf(var + 1e-5f);
    for (int o = lane; o < FIN; o += 32) {
        float x = cs[wr][o];
        out[((size_t)b*NN + n0 + wr)*FIN + o] = (x - m) * r * g2[o] + b2[o];
    }
}

// ---------------------------------------------------------------------------
extern "C" void kernel_launch(void* const* d_in, const int* in_sizes, int n_in,
                              void* d_out, int out_size)
{
    const float* h    = (const float*)d_in[0];
    const int*   adj  = (const int*)  d_in[1];
    const float* W    = (const float*)d_in[2];
    const float* We1  = (const float*)d_in[3];
    const float* be1  = (const float*)d_in[4];
    const float* Wa1  = (const float*)d_in[5];
    const float* ba1  = (const float*)d_in[6];
    const float* wa2  = (const float*)d_in[7];
    const float* ba2  = (const float*)d_in[8];
    const float* ln_g = (const float*)d_in[9];
    const float* ln_b = (const float*)d_in[10];
    const float* Wo   = (const float*)d_in[11];
    const float* bo   = (const float*)d_in[12];
    const float* g2   = (const float*)d_in[13];
    const float* b2   = (const float*)d_in[14];
    float* out = (float*)d_out;

    k1_proj<<<NB*(NN/16), 256>>>(h, W, We1, be1, Wa1, ba1);
    k2_attn<<<NB*NH*NN, 256>>>(Wa1, wa2, ba2, adj, ln_g, ln_b);
    k3_out<<<NB*(NN/8), 256>>>(h, Wo, bo, g2, b2, out);
}

// round 2
// speedup vs baseline: 3.5005x; 3.5005x over previous
#include <cuda_runtime.h>
#include <math.h>

#define NB   8
#define NN   256
#define NH   4
#define HD   64
#define FIN  256
#define ALPHA 0.2f

// Scratch (allocation-free rule: __device__ globals)
__device__ float g_Wh[NB*NH*NN*HD];
__device__ float g_si2[NB*NH*NN*HD];   // si + ba1 + 0.6*(ei@We)
__device__ float g_sj2[NB*NH*NN*HD];   // sj + 0.6*(ej@We)
__device__ float g_ei[NB*NH*NN*HD];
__device__ float g_ej[NB*NH*NN*HD];
__device__ float g_concat[NB*NN*FIN];

// ---- packed f32x2 helpers (Blackwell) ----
__device__ __forceinline__ unsigned long long pack2(float v) {
    unsigned long long r; unsigned u = __float_as_uint(v);
    asm("mov.b64 %0, {%1, %1};" : "=l"(r) : "r"(u));
    return r;
}
__device__ __forceinline__ void fma2(unsigned long long& d,
                                     unsigned long long a, unsigned long long b) {
    asm("fma.rn.f32x2 %0, %1, %2, %0;" : "+l"(d) : "l"(a), "l"(b));
}
__device__ __forceinline__ void unpack2(unsigned long long v, float& lo, float& hi) {
    unsigned a, b;
    asm("mov.b64 {%0, %1}, %2;" : "=r"(a), "=r"(b) : "l"(v));
    lo = __uint_as_float(a); hi = __uint_as_float(b);
}
__device__ __forceinline__ float fabs_alu(float x) {           // LOP3 on alu pipe
    return __uint_as_float(__float_as_uint(x) & 0x7fffffffu);
}

// ---------------------------------------------------------------------------
// Kernel 1: per (b, 8-row tile). Computes Wh, ei, ej, then
// si2 = Wh@Wa + ba1 + 0.6*(ei@We);  sj2 = Wh@Wb + 0.6*(ej@We).
// ---------------------------------------------------------------------------
__global__ __launch_bounds__(256) void k1_proj(
    const float* __restrict__ hin, const float* __restrict__ W,
    const float* __restrict__ We1, const float* __restrict__ be1,
    const float* __restrict__ Wa1, const float* __restrict__ ba1)
{
    const int NT = 8;
    int b  = blockIdx.x >> 5;
    int n0 = (blockIdx.x & 31) * NT;
    int tid = threadIdx.x;
    int head = tid >> 6, d = tid & 63;

    __shared__ float hs [NT][FIN];
    __shared__ float whs[NT][FIN];
    __shared__ float eis[NT][FIN];
    __shared__ float ejs[NT][FIN];

    for (int nn = 0; nn < NT; ++nn)
        hs[nn][tid] = hin[((size_t)(b*NN + n0 + nn))*FIN + tid];
    __syncthreads();

    float accW[NT], accE1[NT], accE2[NT];
#pragma unroll
    for (int nn = 0; nn < NT; ++nn) { accW[nn]=0.f; accE1[nn]=0.f; accE2[nn]=0.f; }

#pragma unroll 4
    for (int f = 0; f < FIN; ++f) {
        float wv = W  [((size_t)head*FIN + f)*HD + d];
        float w1 = We1[((size_t)head*2*FIN + f)*HD + d];
        float w2 = We1[((size_t)head*2*FIN + FIN + f)*HD + d];
#pragma unroll
        for (int nn = 0; nn < NT; ++nn) {
            float hv = hs[nn][f];
            accW[nn]  = fmaf(hv, wv, accW[nn]);
            accE1[nn] = fmaf(hv, w1, accE1[nn]);
            accE2[nn] = fmaf(hv, w2, accE2[nn]);
        }
    }

    float bei = be1[head*HD + d];
#pragma unroll
    for (int nn = 0; nn < NT; ++nn) {
        size_t base = ((size_t)(b*NH + head)*NN + (n0 + nn))*HD + d;
        float e1 = accE1[nn] + bei;
        g_Wh[base] = accW[nn];
        g_ei[base] = e1;
        g_ej[base] = accE2[nn];
        whs[nn][tid] = accW[nn];
        eis[nn][tid] = e1;
        ejs[nn][tid] = accE2[nn];
    }
    __syncthreads();

    float accSi[NT], accSj[NT], accP[NT], accQ[NT];
#pragma unroll
    for (int nn = 0; nn < NT; ++nn) { accSi[nn]=0.f; accSj[nn]=0.f; accP[nn]=0.f; accQ[nn]=0.f; }

    for (int k0 = 0; k0 < HD; k0 += 4) {
        float wa[4], wb[4], we[4];
#pragma unroll
        for (int t = 0; t < 4; ++t) {
            wa[t] = Wa1[((size_t)head*3*HD +          (k0+t))*HD + d];
            wb[t] = Wa1[((size_t)head*3*HD +     HD + (k0+t))*HD + d];
            we[t] = Wa1[((size_t)head*3*HD + 2*HD + (k0+t))*HD + d];
        }
#pragma unroll
        for (int nn = 0; nn < NT; ++nn) {
            float4 whv = *reinterpret_cast<const float4*>(&whs[nn][head*HD + k0]);
            float4 eiv = *reinterpret_cast<const float4*>(&eis[nn][head*HD + k0]);
            float4 ejv = *reinterpret_cast<const float4*>(&ejs[nn][head*HD + k0]);
            accSi[nn] = fmaf(whv.x, wa[0], accSi[nn]); accSi[nn] = fmaf(whv.y, wa[1], accSi[nn]);
            accSi[nn] = fmaf(whv.z, wa[2], accSi[nn]); accSi[nn] = fmaf(whv.w, wa[3], accSi[nn]);
            accSj[nn] = fmaf(whv.x, wb[0], accSj[nn]); accSj[nn] = fmaf(whv.y, wb[1], accSj[nn]);
            accSj[nn] = fmaf(whv.z, wb[2], accSj[nn]); accSj[nn] = fmaf(whv.w, wb[3], accSj[nn]);
            accP [nn] = fmaf(eiv.x, we[0], accP [nn]); accP [nn] = fmaf(eiv.y, we[1], accP [nn]);
            accP [nn] = fmaf(eiv.z, we[2], accP [nn]); accP [nn] = fmaf(eiv.w, we[3], accP [nn]);
            accQ [nn] = fmaf(ejv.x, we[0], accQ [nn]); accQ [nn] = fmaf(ejv.y, we[1], accQ [nn]);
            accQ [nn] = fmaf(ejv.z, we[2], accQ [nn]); accQ [nn] = fmaf(ejv.w, we[3], accQ [nn]);
        }
    }
    float bsi = ba1[head*HD + d];
#pragma unroll
    for (int nn = 0; nn < NT; ++nn) {
        size_t base = ((size_t)(b*NH + head)*NN + (n0 + nn))*HD + d;
        g_si2[base] = accSi[nn] + bsi + 0.6f*accP[nn];
        g_sj2[base] = accSj[nn]       + 0.6f*accQ[nn];
    }
}

// ---------------------------------------------------------------------------
// Kernel 2: one block per (b, head, 4-i tile).  256 threads = 64 j x 4 d-groups.
// e[i,j] = sum_d wa2_d * LR( si2[i,d] + sj2[j,d] + sum_k |ei_ik+ej_jk| * 0.4We[k,d] )
// then masked softmax, hp = attn@Wh, per-head layernorm.
// ---------------------------------------------------------------------------
__global__ __launch_bounds__(256, 2) void k2_attn(
    const float* __restrict__ Wa1, const float* __restrict__ wa2,
    const float* __restrict__ ba2, const int* __restrict__ adj,
    const float* __restrict__ ln_g, const float* __restrict__ ln_b)
{
    int bx   = blockIdx.x;
    int it   = bx & 63;             // i-tile (4 rows)
    int head = (bx >> 6) & 3;
    int b    = bx >> 8;
    int i0   = it * 4;
    int tid  = threadIdx.x;
    int jj   = tid >> 2;            // 0..63
    int dg   = tid & 3;             // 0..3
    int db   = dg * 16;

    __shared__ float ej_s[64][65];
    __shared__ __align__(16) float We_s[64][64];      // 0.4 * We
    __shared__ float ei_s[4][64];
    __shared__ float si2_s[4][64];
    __shared__ float wa2_s[64];
    __shared__ float e_s[4][256];
    __shared__ float hp_s[4][4][64];
    __shared__ float red_s[16];

    size_t bh = (size_t)(b*NH + head);
    const float* ej_base  = g_ej  + bh*NN*HD;
    const float* sj_base  = g_sj2 + bh*NN*HD;
    const float* wh_base  = g_Wh  + bh*NN*HD;

    for (int t = tid; t < 64*64; t += 256)
        We_s[t >> 6][t & 63] = 0.4f * Wa1[((size_t)head*3*HD + 2*HD + (t >> 6))*HD + (t & 63)];
    {
        int ii = tid >> 6, dd = tid & 63;
        ei_s [ii][dd] = g_ei [(bh*NN + i0 + ii)*HD + dd];
        si2_s[ii][dd] = g_si2[(bh*NN + i0 + ii)*HD + dd];
    }
    if (tid < 64) wa2_s[tid] = wa2[head*HD + tid];
    float ba2v = ba2[head];

    for (int jt = 0; jt < 4; ++jt) {
        __syncthreads();
        int j0 = jt * 64;
        for (int t = tid; t < 64*64; t += 256)
            ej_s[t >> 6][t & 63] = ej_base[(size_t)(j0 + (t >> 6))*HD + (t & 63)];
        __syncthreads();

        unsigned long long acc[4][8];
#pragma unroll
        for (int ii = 0; ii < 4; ++ii)
#pragma unroll
            for (int p = 0; p < 8; ++p) acc[ii][p] = 0ull;

#pragma unroll 2
        for (int k = 0; k < 64; ++k) {
            float ejv = ej_s[jj][k];
            unsigned long long evp[4];
#pragma unroll
            for (int ii = 0; ii < 4; ++ii) {
                float s  = ei_s[ii][k] + ejv;
                evp[ii] = pack2(fabs_alu(s));
            }
            const ulonglong2* wp = reinterpret_cast<const ulonglong2*>(&We_s[k][db]);
            ulonglong2 wA = wp[0], wB = wp[1], wC = wp[2], wD = wp[3];
#pragma unroll
            for (int ii = 0; ii < 4; ++ii) {
                fma2(acc[ii][0], evp[ii], wA.x); fma2(acc[ii][1], evp[ii], wA.y);
                fma2(acc[ii][2], evp[ii], wB.x); fma2(acc[ii][3], evp[ii], wB.y);
                fma2(acc[ii][4], evp[ii], wC.x); fma2(acc[ii][5], evp[ii], wC.y);
                fma2(acc[ii][6], evp[ii], wD.x); fma2(acc[ii][7], evp[ii], wD.y);
            }
        }

        // epilogue for this j-tile
        float sjf[16];
        {
            const float4* sj4 = reinterpret_cast<const float4*>(sj_base + (size_t)(j0 + jj)*HD + db);
            *reinterpret_cast<float4*>(&sjf[0])  = sj4[0];
            *reinterpret_cast<float4*>(&sjf[4])  = sj4[1];
            *reinterpret_cast<float4*>(&sjf[8])  = sj4[2];
            *reinterpret_cast<float4*>(&sjf[12]) = sj4[3];
        }
#pragma unroll
        for (int ii = 0; ii < 4; ++ii) {
            float pe = 0.f;
#pragma unroll
            for (int p = 0; p < 8; ++p) {
                float lo, hi; unpack2(acc[ii][p], lo, hi);
                float c0 = si2_s[ii][db + 2*p]     + sjf[2*p]     + lo;
                float c1 = si2_s[ii][db + 2*p + 1] + sjf[2*p + 1] + hi;
                float h0 = fmaxf(c0, ALPHA*c0);
                float h1 = fmaxf(c1, ALPHA*c1);
                pe = fmaf(h0, wa2_s[db + 2*p],     pe);
                pe = fmaf(h1, wa2_s[db + 2*p + 1], pe);
            }
            pe += __shfl_xor_sync(0xffffffffu, pe, 1);
            pe += __shfl_xor_sync(0xffffffffu, pe, 2);
            if (dg == 0) {
                int j = j0 + jj;
                int a = adj[((size_t)b*NN + i0 + ii)*NN + j];
                e_s[ii][j] = (a == 0) ? -1e9f : (pe + ba2v);
            }
        }
    }
    __syncthreads();

    // ---- masked softmax: 64-thread group per i ----
    int ii2 = tid >> 6, t64 = tid & 63, lane = tid & 31, wgrp = (tid >> 5) & 1;
    {
        float vals[4]; float mx = -1e30f;
#pragma unroll
        for (int s = 0; s < 4; ++s) { vals[s] = e_s[ii2][t64 + 64*s]; mx = fmaxf(mx, vals[s]); }
#pragma unroll
        for (int o = 16; o; o >>= 1) mx = fmaxf(mx, __shfl_xor_sync(0xffffffffu, mx, o));
        if (lane == 0) red_s[ii2*2 + wgrp] = mx;
        __syncthreads();
        mx = fmaxf(red_s[ii2*2], red_s[ii2*2 + 1]);
        float se = 0.f;
#pragma unroll
        for (int s = 0; s < 4; ++s) { vals[s] = __expf(vals[s] - mx); se += vals[s]; }
#pragma unroll
        for (int o = 16; o; o >>= 1) se += __shfl_xor_sync(0xffffffffu, se, o);
        if (lane == 0) red_s[8 + ii2*2 + wgrp] = se;
        __syncthreads();
        float inv = 1.0f / (red_s[8 + ii2*2] + red_s[9 + ii2*2]);
#pragma unroll
        for (int s = 0; s < 4; ++s) e_s[ii2][t64 + 64*s] = vals[s] * inv;
    }
    __syncthreads();

    // ---- hp[ii][d] = sum_j attn[ii][j] * Wh[j][d]  (Wh loads shared over ii) ----
    {
        int q = tid >> 6, d = tid & 63;
        float hpa[4] = {0.f, 0.f, 0.f, 0.f};
        const float* whq = wh_base + (size_t)q*64*HD + d;
#pragma unroll 4
        for (int j = 0; j < 64; ++j) {
            float wv = whq[(size_t)j*HD];
            hpa[0] = fmaf(e_s[0][q*64 + j], wv, hpa[0]);
            hpa[1] = fmaf(e_s[1][q*64 + j], wv, hpa[1]);
            hpa[2] = fmaf(e_s[2][q*64 + j], wv, hpa[2]);
            hpa[3] = fmaf(e_s[3][q*64 + j], wv, hpa[3]);
        }
#pragma unroll
        for (int ii = 0; ii < 4; ++ii) hp_s[q][ii][d] = hpa[ii];
    }
    __syncthreads();

    // ---- per-head layernorm (64-thread group per i) ----
    {
        float hv = hp_s[0][ii2][t64] + hp_s[1][ii2][t64] + hp_s[2][ii2][t64] + hp_s[3][ii2][t64];
        float s1 = hv, s2 = hv*hv;
#pragma unroll
        for (int o = 16; o; o >>= 1) {
            s1 += __shfl_xor_sync(0xffffffffu, s1, o);
            s2 += __shfl_xor_sync(0xffffffffu, s2, o);
        }
        __syncthreads();
        if (lane == 0) { red_s[2*ii2 + wgrp] = s1; red_s[8 + 2*ii2 + wgrp] = s2; }
        __syncthreads();
        float m   = (red_s[2*ii2] + red_s[2*ii2 + 1]) * (1.0f/64.0f);
        float var = (red_s[8 + 2*ii2] + red_s[9 + 2*ii2]) * (1.0f/64.0f) - m*m;
        float r   = rsqrtf(var + 1e-5f);
        float y   = (hv - m) * r * ln_g[head*HD + t64] + ln_b[head*HD + t64];
        g_concat[((size_t)b*NN + i0 + ii2)*FIN + head*HD + t64] = y;
    }
}

// ---------------------------------------------------------------------------
// Kernel 3: out = layernorm(concat @ Wo + bo + h), blocks of 8 rows.
// ---------------------------------------------------------------------------
__global__ __launch_bounds__(256) void k3_out(
    const float* __restrict__ hin, const float* __restrict__ Wo,
    const float* __restrict__ bo,  const float* __restrict__ g2,
    const float* __restrict__ b2,  float* __restrict__ out)
{
    const int NT = 8;
    int b  = blockIdx.x / (NN / NT);
    int n0 = (blockIdx.x % (NN / NT)) * NT;
    int tid = threadIdx.x;

    __shared__ float cs[NT][FIN];
    __shared__ float hs2[NT][FIN];

    for (int nn = 0; nn < NT; ++nn) {
        cs[nn][tid]  = g_concat[((size_t)b*NN + n0 + nn)*FIN + tid];
        hs2[nn][tid] = hin     [((size_t)b*NN + n0 + nn)*FIN + tid];
    }
    __syncthreads();

    float acc[NT];
    float bv = bo[tid];
#pragma unroll
    for (int nn = 0; nn < NT; ++nn) acc[nn] = bv;

#pragma unroll 4
    for (int f = 0; f < FIN; ++f) {
        float w = Wo[(size_t)f*FIN + tid];
#pragma unroll
        for (int nn = 0; nn < NT; ++nn)
            acc[nn] = fmaf(cs[nn][f], w, acc[nn]);
    }
    __syncthreads();
    for (int nn = 0; nn < NT; ++nn)
        cs[nn][tid] = acc[nn] + hs2[nn][tid];
    __syncthreads();

    int wr = tid >> 5, lane = tid & 31;
    float s1 = 0.f, s2 = 0.f;
    for (int o = lane; o < FIN; o += 32) {
        float x = cs[wr][o]; s1 += x; s2 += x*x;
    }
#pragma unroll
    for (int o = 16; o; o >>= 1) {
        s1 += __shfl_xor_sync(0xffffffffu, s1, o);
        s2 += __shfl_xor_sync(0xffffffffu, s2, o);
    }
    float m   = s1 * (1.0f/256.0f);
    float var = s2 * (1.0f/256.0f) - m*m;
    float r   = rsqrtf(var + 1e-5f);
    for (int o = lane; o < FIN; o += 32) {
        float x = cs[wr][o];
        out[((size_t)b*NN + n0 + wr)*FIN + o] = (x - m) * r * g2[o] + b2[o];
    }
}

// ---------------------------------------------------------------------------
extern "C" void kernel_launch(void* const* d_in, const int* in_sizes, int n_in,
                              void* d_out, int out_size)
{
    const float* h    = (const float*)d_in[0];
    const int*   adj  = (const int*)  d_in[1];
    const float* W    = (const float*)d_in[2];
    const float* We1  = (const float*)d_in[3];
    const float* be1  = (const float*)d_in[4];
    const float* Wa1  = (const float*)d_in[5];
    const float* ba1  = (const float*)d_in[6];
    const float* wa2  = (const float*)d_in[7];
    const float* ba2  = (const float*)d_in[8];
    const float* ln_g = (const float*)d_in[9];
    const float* ln_b = (const float*)d_in[10];
    const float* Wo   = (const float*)d_in[11];
    const float* bo   = (const float*)d_in[12];
    const float* g2   = (const float*)d_in[13];
    const float* b2   = (const float*)d_in[14];
    float* out = (float*)d_out;

    k1_proj<<<NB*(NN/8), 256>>>(h, W, We1, be1, Wa1, ba1);
    k2_attn<<<NB*NH*(NN/4), 256>>>(Wa1, wa2, ba2, adj, ln_g, ln_b);
    k3_out<<<NB*(NN/8), 256>>>(h, Wo, bo, g2, b2, out);
}

// round 4
// speedup vs baseline: 8.4516x; 2.4144x over previous
#include <cuda_runtime.h>
#include <math.h>
#include <stdint.h>

#define NB   8
#define NN   256
#define NH   4
#define HD   64
#define FIN  256
#define ALPHA 0.2f

// ---------------- scratch (__device__ globals; no allocs allowed) ----------
__device__ float g_Wh [NB*NH*NN*HD];
__device__ float g_si2[NB*NH*NN*HD];   // si + ba1 + 0.6*(ei@We)
__device__ float g_sj2[NB*NH*NN*HD];   // sj + 0.6*(ej@We)
__device__ float g_ei [NB*NH*NN*HD];
__device__ float g_ej [NB*NH*NN*HD];
__device__ float g_e  [NB*NH*NN*NN];   // raw e (pre-bias, pre-mask)
__device__ float g_concat[NB*NN*FIN];

// ---------------- mma.sync helpers (base ISA, works on sm_103) -------------
__device__ __forceinline__ uint32_t cvt_tf32(float x) {
    uint32_t r;
    asm("cvt.rna.tf32.f32 %0, %1;" : "=r"(r) : "f"(x));
    return r;
}
__device__ __forceinline__ void mma1688(float& c0, float& c1, float& c2, float& c3,
                                        uint32_t a0, uint32_t a1, uint32_t a2, uint32_t a3,
                                        uint32_t b0, uint32_t b1) {
    asm volatile("mma.sync.aligned.m16n8k8.row.col.f32.tf32.tf32.f32 "
                 "{%0,%1,%2,%3}, {%4,%5,%6,%7}, {%8,%9}, {%0,%1,%2,%3};"
                 : "+f"(c0), "+f"(c1), "+f"(c2), "+f"(c3)
                 : "r"(a0), "r"(a1), "r"(a2), "r"(a3), "r"(b0), "r"(b1));
}
__device__ __forceinline__ float fabs_bits(float x) {
    return __uint_as_float(__float_as_uint(x) & 0x7fffffffu);
}

// dynamic smem layout for t2 (float offsets)
#define EJ_PITCH 68
#define O_EJ   0
#define O_SJ   (256*EJ_PITCH)            // 17408
#define O_WE   (2*256*EJ_PITCH)          // 34816
#define O_EI   (O_WE + 64*64)            // 38912
#define O_SI   (O_EI + 16*64)            // 39936
#define O_PE   (O_SI + 16*64)            // 40960
#define T2_FLOATS (O_PE + 2*256)         // 41472
#define T2_BYTES  (T2_FLOATS*4)          // 165888

// ---------------------------------------------------------------------------
// Kernel 1: projections + algebraic fold (LR(x)=0.6x+0.4|x| for x-linear part).
// ---------------------------------------------------------------------------
__global__ __launch_bounds__(256) void k1_proj(
    const float* __restrict__ hin, const float* __restrict__ W,
    const float* __restrict__ We1, const float* __restrict__ be1,
    const float* __restrict__ Wa1, const float* __restrict__ ba1)
{
    const int NT = 8;
    int b  = blockIdx.x >> 5;
    int n0 = (blockIdx.x & 31) * NT;
    int tid = threadIdx.x;
    int head = tid >> 6, d = tid & 63;

    __shared__ float hs [NT][FIN];
    __shared__ float whs[NT][FIN];
    __shared__ float eis[NT][FIN];
    __shared__ float ejs[NT][FIN];

    for (int nn = 0; nn < NT; ++nn)
        hs[nn][tid] = hin[((size_t)(b*NN + n0 + nn))*FIN + tid];
    __syncthreads();

    float accW[NT], accE1[NT], accE2[NT];
#pragma unroll
    for (int nn = 0; nn < NT; ++nn) { accW[nn]=0.f; accE1[nn]=0.f; accE2[nn]=0.f; }

#pragma unroll 4
    for (int f = 0; f < FIN; ++f) {
        float wv = W  [((size_t)head*FIN + f)*HD + d];
        float w1 = We1[((size_t)head*2*FIN + f)*HD + d];
        float w2 = We1[((size_t)head*2*FIN + FIN + f)*HD + d];
#pragma unroll
        for (int nn = 0; nn < NT; ++nn) {
            float hv = hs[nn][f];
            accW[nn]  = fmaf(hv, wv, accW[nn]);
            accE1[nn] = fmaf(hv, w1, accE1[nn]);
            accE2[nn] = fmaf(hv, w2, accE2[nn]);
        }
    }

    float bei = be1[head*HD + d];
#pragma unroll
    for (int nn = 0; nn < NT; ++nn) {
        size_t base = ((size_t)(b*NH + head)*NN + (n0 + nn))*HD + d;
        float e1 = accE1[nn] + bei;
        g_Wh[base] = accW[nn];
        g_ei[base] = e1;
        g_ej[base] = accE2[nn];
        whs[nn][tid] = accW[nn];
        eis[nn][tid] = e1;
        ejs[nn][tid] = accE2[nn];
    }
    __syncthreads();

    float accSi[NT], accSj[NT], accP[NT], accQ[NT];
#pragma unroll
    for (int nn = 0; nn < NT; ++nn) { accSi[nn]=0.f; accSj[nn]=0.f; accP[nn]=0.f; accQ[nn]=0.f; }

    for (int k0 = 0; k0 < HD; k0 += 4) {
        float wa[4], wb[4], we[4];
#pragma unroll
        for (int t = 0; t < 4; ++t) {
            wa[t] = Wa1[((size_t)head*3*HD +          (k0+t))*HD + d];
            wb[t] = Wa1[((size_t)head*3*HD +     HD + (k0+t))*HD + d];
            we[t] = Wa1[((size_t)head*3*HD + 2*HD + (k0+t))*HD + d];
        }
#pragma unroll
        for (int nn = 0; nn < NT; ++nn) {
            float4 whv = *reinterpret_cast<const float4*>(&whs[nn][head*HD + k0]);
            float4 eiv = *reinterpret_cast<const float4*>(&eis[nn][head*HD + k0]);
            float4 ejv = *reinterpret_cast<const float4*>(&ejs[nn][head*HD + k0]);
            accSi[nn] = fmaf(whv.x, wa[0], accSi[nn]); accSi[nn] = fmaf(whv.y, wa[1], accSi[nn]);
            accSi[nn] = fmaf(whv.z, wa[2], accSi[nn]); accSi[nn] = fmaf(whv.w, wa[3], accSi[nn]);
            accSj[nn] = fmaf(whv.x, wb[0], accSj[nn]); accSj[nn] = fmaf(whv.y, wb[1], accSj[nn]);
            accSj[nn] = fmaf(whv.z, wb[2], accSj[nn]); accSj[nn] = fmaf(whv.w, wb[3], accSj[nn]);
            accP [nn] = fmaf(eiv.x, we[0], accP [nn]); accP [nn] = fmaf(eiv.y, we[1], accP [nn]);
            accP [nn] = fmaf(eiv.z, we[2], accP [nn]); accP [nn] = fmaf(eiv.w, we[3], accP [nn]);
            accQ [nn] = fmaf(ejv.x, we[0], accQ [nn]); accQ [nn] = fmaf(ejv.y, we[1], accQ [nn]);
            accQ [nn] = fmaf(ejv.z, we[2], accQ [nn]); accQ [nn] = fmaf(ejv.w, we[3], accQ [nn]);
        }
    }
    float bsi = ba1[head*HD + d];
#pragma unroll
    for (int nn = 0; nn < NT; ++nn) {
        size_t base = ((size_t)(b*NH + head)*NN + (n0 + nn))*HD + d;
        g_si2[base] = accSi[nn] + bsi + 0.6f*accP[nn];
        g_sj2[base] = accSj[nn]       + 0.6f*accQ[nn];
    }
}

// ---------------------------------------------------------------------------
// t2: edge GEMM via mma.sync m16n8k8 tf32.
// Block = (b, head, 16 i's). 8 warps = 4 j-groups (64 j) x 2 d-groups (32 d).
// Per i:  D[j,d] = si2[i,d] + sum_k |ei[i,k]+ej[j,k]| * (0.4*We)[k,d]
//         e[i,j] = sum_d wa2[d] * LR(D[j,d] + sj2[j,d])        -> g_e
// ---------------------------------------------------------------------------
__global__ __launch_bounds__(256) void t2_edge(
    const float* __restrict__ Wa1, const float* __restrict__ wa2)
{
    extern __shared__ float sm[];

    int bx   = blockIdx.x;
    int it   = bx & 15;
    int head = (bx >> 4) & 3;
    int b    = bx >> 6;
    int i0   = it * 16;
    int tid  = threadIdx.x;
    int wid  = tid >> 5, lane = tid & 31;
    int gid  = lane >> 2, tig = lane & 3;   // groupID / thread-in-group
    int jg   = wid & 3;                     // j-group (64 rows)
    int dg   = wid >> 2;                    // d-group (32 cols)
    int d0w  = dg * 32;

    size_t bh = (size_t)(b*NH + head);
    const float* ej_base = g_ej  + bh*NN*HD;
    const float* sj_base = g_sj2 + bh*NN*HD;

    // ---- stage: ej, sj2 (padded rows), We' (tf32-rounded), ei, si2 ----
    for (int t = tid*4; t < NN*HD; t += 256*4) {
        int j = t >> 6, k = t & 63;
        *reinterpret_cast<float4*>(&sm[O_EJ + j*EJ_PITCH + k]) =
            *reinterpret_cast<const float4*>(ej_base + t);
        *reinterpret_cast<float4*>(&sm[O_SJ + j*EJ_PITCH + k]) =
            *reinterpret_cast<const float4*>(sj_base + t);
    }
    for (int t = tid; t < 64*64; t += 256) {
        int k = t >> 6, d = t & 63;
        float v = 0.4f * Wa1[((size_t)head*3*HD + 2*HD + k)*HD + d];
        sm[O_WE + t] = __uint_as_float(cvt_tf32(v));
    }
    for (int t = tid; t < 16*64; t += 256) {
        int ii = t >> 6, d = t & 63;
        sm[O_EI + t] = g_ei [(bh*NN + i0 + ii)*HD + d];
        sm[O_SI + t] = g_si2[(bh*NN + i0 + ii)*HD + d];
    }
    __syncthreads();

    // ---- preload B fragments (resident whole block): b[ks][nt][2] ----
    uint32_t bf[8][4][2];
#pragma unroll
    for (int ks = 0; ks < 8; ++ks)
#pragma unroll
        for (int nt = 0; nt < 4; ++nt) {
            int dd = d0w + nt*8 + gid;
            bf[ks][nt][0] = __float_as_uint(sm[O_WE + (ks*8 + tig)*64     + dd]);
            bf[ks][nt][1] = __float_as_uint(sm[O_WE + (ks*8 + tig + 4)*64 + dd]);
        }

    // ---- preload wa2 for this thread's d-set ----
    float wa2r[8];
#pragma unroll
    for (int nt = 0; nt < 4; ++nt) {
        int dd = d0w + nt*8 + 2*tig;
        wa2r[nt*2]     = wa2[head*HD + dd];
        wa2r[nt*2 + 1] = wa2[head*HD + dd + 1];
    }

    for (int ii = 0; ii < 16; ++ii) {
        // si2 accumulator-init values for this i
        float2 s2[4];
#pragma unroll
        for (int nt = 0; nt < 4; ++nt)
            s2[nt] = *reinterpret_cast<const float2*>(&sm[O_SI + ii*64 + d0w + nt*8 + 2*tig]);

#pragma unroll
        for (int jt = 0; jt < 4; ++jt) {
            int j0 = jg*64 + jt*16;
            float acc[4][4];
#pragma unroll
            for (int nt = 0; nt < 4; ++nt) {
                acc[nt][0] = s2[nt].x; acc[nt][1] = s2[nt].y;
                acc[nt][2] = s2[nt].x; acc[nt][3] = s2[nt].y;
            }

#pragma unroll
            for (int ks = 0; ks < 8; ++ks) {
                int k0 = ks*8;
                float eA = sm[O_EI + ii*64 + k0 + tig];
                float eB = sm[O_EI + ii*64 + k0 + tig + 4];
                uint32_t a0 = cvt_tf32(fabs_bits(sm[O_EJ + (j0+gid  )*EJ_PITCH + k0 + tig    ] + eA));
                uint32_t a1 = cvt_tf32(fabs_bits(sm[O_EJ + (j0+gid+8)*EJ_PITCH + k0 + tig    ] + eA));
                uint32_t a2 = cvt_tf32(fabs_bits(sm[O_EJ + (j0+gid  )*EJ_PITCH + k0 + tig + 4] + eB));
                uint32_t a3 = cvt_tf32(fabs_bits(sm[O_EJ + (j0+gid+8)*EJ_PITCH + k0 + tig + 4] + eB));
#pragma unroll
                for (int nt = 0; nt < 4; ++nt)
                    mma1688(acc[nt][0], acc[nt][1], acc[nt][2], acc[nt][3],
                            a0, a1, a2, a3, bf[ks][nt][0], bf[ks][nt][1]);
            }

            // epilogue for this (i, j-tile): rows r0, r1
            int r0 = j0 + gid, r1 = r0 + 8;
            float pe0 = 0.f, pe1 = 0.f;
#pragma unroll
            for (int nt = 0; nt < 4; ++nt) {
                int dd = d0w + nt*8 + 2*tig;
                float2 sj0 = *reinterpret_cast<const float2*>(&sm[O_SJ + r0*EJ_PITCH + dd]);
                float2 sj1 = *reinterpret_cast<const float2*>(&sm[O_SJ + r1*EJ_PITCH + dd]);
                float v00 = acc[nt][0] + sj0.x, v01 = acc[nt][1] + sj0.y;
                float v10 = acc[nt][2] + sj1.x, v11 = acc[nt][3] + sj1.y;
                pe0 = fmaf(fmaxf(v00, ALPHA*v00), wa2r[nt*2],     pe0);
                pe0 = fmaf(fmaxf(v01, ALPHA*v01), wa2r[nt*2 + 1], pe0);
                pe1 = fmaf(fmaxf(v10, ALPHA*v10), wa2r[nt*2],     pe1);
                pe1 = fmaf(fmaxf(v11, ALPHA*v11), wa2r[nt*2 + 1], pe1);
            }
            pe0 += __shfl_xor_sync(0xffffffffu, pe0, 1);
            pe0 += __shfl_xor_sync(0xffffffffu, pe0, 2);
            pe1 += __shfl_xor_sync(0xffffffffu, pe1, 1);
            pe1 += __shfl_xor_sync(0xffffffffu, pe1, 2);
            if (tig == 0) {
                sm[O_PE + dg*256 + r0] = pe0;
                sm[O_PE + dg*256 + r1] = pe1;
            }
        }
        __syncthreads();
        {
            float e = sm[O_PE + tid] + sm[O_PE + 256 + tid];
            g_e[(bh*NN + i0 + ii)*NN + tid] = e;
        }
        __syncthreads();
    }
}

// ---------------------------------------------------------------------------
// k2b: mask+bias+softmax over j, hp = attn @ Wh, per-head layernorm.
// ---------------------------------------------------------------------------
__global__ __launch_bounds__(256) void k2b_soft(
    const int* __restrict__ adj, const float* __restrict__ ba2,
    const float* __restrict__ ln_g, const float* __restrict__ ln_b)
{
    int bx   = blockIdx.x;
    int it   = bx & 63;
    int head = (bx >> 6) & 3;
    int b    = bx >> 8;
    int i0   = it * 4;
    int tid  = threadIdx.x;

    __shared__ float e_s[4][256];
    __shared__ float hp_s[4][4][64];
    __shared__ float red_s[16];

    size_t bh = (size_t)(b*NH + head);
    const float* wh_base = g_Wh + bh*NN*HD;
    float bav = ba2[head];

#pragma unroll
    for (int s = 0; s < 4; ++s) {
        int idx = tid + s*256;
        int row = idx >> 8, j = idx & 255;
        float pe = g_e[(bh*NN + i0 + row)*NN + j];
        int a = adj[((size_t)b*NN + i0 + row)*NN + j];
        e_s[row][j] = (a == 0) ? -1e9f : (pe + bav);
    }
    __syncthreads();

    int ii2 = tid >> 6, t64 = tid & 63, lane = tid & 31, wgrp = (tid >> 5) & 1;
    {
        float vals[4]; float mx = -1e30f;
#pragma unroll
        for (int s = 0; s < 4; ++s) { vals[s] = e_s[ii2][t64 + 64*s]; mx = fmaxf(mx, vals[s]); }
#pragma unroll
        for (int o = 16; o; o >>= 1) mx = fmaxf(mx, __shfl_xor_sync(0xffffffffu, mx, o));
        if (lane == 0) red_s[ii2*2 + wgrp] = mx;
        __syncthreads();
        mx = fmaxf(red_s[ii2*2], red_s[ii2*2 + 1]);
        float se = 0.f;
#pragma unroll
        for (int s = 0; s < 4; ++s) { vals[s] = __expf(vals[s] - mx); se += vals[s]; }
#pragma unroll
        for (int o = 16; o; o >>= 1) se += __shfl_xor_sync(0xffffffffu, se, o);
        if (lane == 0) red_s[8 + ii2*2 + wgrp] = se;
        __syncthreads();
        float inv = 1.0f / (red_s[8 + ii2*2] + red_s[9 + ii2*2]);
#pragma unroll
        for (int s = 0; s < 4; ++s) e_s[ii2][t64 + 64*s] = vals[s] * inv;
    }
    __syncthreads();

    {
        int q = tid >> 6, d = tid & 63;
        float hpa[4] = {0.f, 0.f, 0.f, 0.f};
        const float* whq = wh_base + (size_t)q*64*HD + d;
#pragma unroll 4
        for (int j = 0; j < 64; ++j) {
            float wv = whq[(size_t)j*HD];
            hpa[0] = fmaf(e_s[0][q*64 + j], wv, hpa[0]);
            hpa[1] = fmaf(e_s[1][q*64 + j], wv, hpa[1]);
            hpa[2] = fmaf(e_s[2][q*64 + j], wv, hpa[2]);
            hpa[3] = fmaf(e_s[3][q*64 + j], wv, hpa[3]);
        }
#pragma unroll
        for (int ii = 0; ii < 4; ++ii) hp_s[q][ii][d] = hpa[ii];
    }
    __syncthreads();

    {
        float hv = hp_s[0][ii2][t64] + hp_s[1][ii2][t64] + hp_s[2][ii2][t64] + hp_s[3][ii2][t64];
        float s1 = hv, s2 = hv*hv;
#pragma unroll
        for (int o = 16; o; o >>= 1) {
            s1 += __shfl_xor_sync(0xffffffffu, s1, o);
            s2 += __shfl_xor_sync(0xffffffffu, s2, o);
        }
        __syncthreads();
        if (lane == 0) { red_s[2*ii2 + wgrp] = s1; red_s[8 + 2*ii2 + wgrp] = s2; }
        __syncthreads();
        float m   = (red_s[2*ii2] + red_s[2*ii2 + 1]) * (1.0f/64.0f);
        float var = (red_s[8 + 2*ii2] + red_s[9 + 2*ii2]) * (1.0f/64.0f) - m*m;
        float r   = rsqrtf(var + 1e-5f);
        float y   = (hv - m) * r * ln_g[head*HD + t64] + ln_b[head*HD + t64];
        g_concat[((size_t)b*NN + i0 + ii2)*FIN + head*HD + t64] = y;
    }
}

// ---------------------------------------------------------------------------
// Kernel 3: out = layernorm(concat @ Wo + bo + h).
// ---------------------------------------------------------------------------
__global__ __launch_bounds__(256) void k3_out(
    const float* __restrict__ hin, const float* __restrict__ Wo,
    const float* __restrict__ bo,  const float* __restrict__ g2,
    const float* __restrict__ b2,  float* __restrict__ out)
{
    const int NT = 8;
    int b  = blockIdx.x / (NN / NT);
    int n0 = (blockIdx.x % (NN / NT)) * NT;
    int tid = threadIdx.x;

    __shared__ float cs[NT][FIN];
    __shared__ float hs2[NT][FIN];

    for (int nn = 0; nn < NT; ++nn) {
        cs[nn][tid]  = g_concat[((size_t)b*NN + n0 + nn)*FIN + tid];
        hs2[nn][tid] = hin     [((size_t)b*NN + n0 + nn)*FIN + tid];
    }
    __syncthreads();

    float acc[NT];
    float bv = bo[tid];
#pragma unroll
    for (int nn = 0; nn < NT; ++nn) acc[nn] = bv;

#pragma unroll 4
    for (int f = 0; f < FIN; ++f) {
        float w = Wo[(size_t)f*FIN + tid];
#pragma unroll
        for (int nn = 0; nn < NT; ++nn)
            acc[nn] = fmaf(cs[nn][f], w, acc[nn]);
    }
    __syncthreads();
    for (int nn = 0; nn < NT; ++nn)
        cs[nn][tid] = acc[nn] + hs2[nn][tid];
    __syncthreads();

    int wr = tid >> 5, lane = tid & 31;
    float s1 = 0.f, s2 = 0.f;
    for (int o = lane; o < FIN; o += 32) {
        float x = cs[wr][o]; s1 += x; s2 += x*x;
    }
#pragma unroll
    for (int o = 16; o; o >>= 1) {
        s1 += __shfl_xor_sync(0xffffffffu, s1, o);
        s2 += __shfl_xor_sync(0xffffffffu, s2, o);
    }
    float m   = s1 * (1.0f/256.0f);
    float var = s2 * (1.0f/256.0f) - m*m;
    float r   = rsqrtf(var + 1e-5f);
    for (int o = lane; o < FIN; o += 32) {
        float x = cs[wr][o];
        out[((size_t)b*NN + n0 + wr)*FIN + o] = (x - m) * r * g2[o] + b2[o];
    }
}

// ---------------------------------------------------------------------------
extern "C" void kernel_launch(void* const* d_in, const int* in_sizes, int n_in,
                              void* d_out, int out_size)
{
    const float* h    = (const float*)d_in[0];
    const int*   adj  = (const int*)  d_in[1];
    const float* W    = (const float*)d_in[2];
    const float* We1  = (const float*)d_in[3];
    const float* be1  = (const float*)d_in[4];
    const float* Wa1  = (const float*)d_in[5];
    const float* ba1  = (const float*)d_in[6];
    const float* wa2  = (const float*)d_in[7];
    const float* ba2  = (const float*)d_in[8];
    const float* ln_g = (const float*)d_in[9];
    const float* ln_b = (const float*)d_in[10];
    const float* Wo   = (const float*)d_in[11];
    const float* bo   = (const float*)d_in[12];
    const float* g2   = (const float*)d_in[13];
    const float* b2   = (const float*)d_in[14];
    float* out = (float*)d_out;

    cudaFuncSetAttribute(t2_edge, cudaFuncAttributeMaxDynamicSharedMemorySize, T2_BYTES);

    k1_proj <<<NB*(NN/8), 256>>>(h, W, We1, be1, Wa1, ba1);
    t2_edge <<<NB*NH*(NN/16), 256, T2_BYTES>>>(Wa1, wa2);
    k2b_soft<<<NB*NH*(NN/4), 256>>>(adj, ba2, ln_g, ln_b);
    k3_out  <<<NB*(NN/8), 256>>>(h, Wo, bo, g2, b2, out);
}

// round 5
// speedup vs baseline: 11.5260x; 1.3638x over previous
#include <cuda_runtime.h>
#include <math.h>
#include <stdint.h>

#define NB   8
#define NN   256
#define NH   4
#define HD   64
#define FIN  256
#define ALPHA 0.2f

// ---------------- scratch (__device__ globals; no allocs allowed) ----------
__device__ float g_Wh [NB*NH*NN*HD];
__device__ float g_si2[NB*NH*NN*HD];   // si + ba1 + 0.6*(ei@We)
__device__ float g_sj2[NB*NH*NN*HD];   // sj + 0.6*(ej@We)
__device__ float g_ei [NB*NH*NN*HD];
__device__ float g_ej [NB*NH*NN*HD];
__device__ float g_concat[NB*NN*FIN];

// ---------------- packed helpers -------------------------------------------
__device__ __forceinline__ unsigned long long pack2(float v) {
    unsigned long long r; unsigned u = __float_as_uint(v);
    asm("mov.b64 %0, {%1, %1};" : "=l"(r) : "r"(u));
    return r;
}
__device__ __forceinline__ void fma2(unsigned long long& d,
                                     unsigned long long a, unsigned long long b) {
    asm("fma.rn.f32x2 %0, %1, %2, %0;" : "+l"(d) : "l"(a), "l"(b));
}
__device__ __forceinline__ void unpack2(unsigned long long v, float& lo, float& hi) {
    unsigned a, b;
    asm("mov.b64 {%0, %1}, %2;" : "=r"(a), "=r"(b) : "l"(v));
    lo = __uint_as_float(a); hi = __uint_as_float(b);
}
__device__ __forceinline__ uint32_t packbf(float lo, float hi) {   // low half = lo
    uint32_t r;
    asm("cvt.rn.bf16x2.f32 %0, %1, %2;" : "=r"(r) : "f"(hi), "f"(lo));
    return r;
}
__device__ __forceinline__ uint32_t hadd2(uint32_t a, uint32_t b) {
    uint32_t r;
    asm("add.rn.bf16x2 %0, %1, %2;" : "=r"(r) : "r"(a), "r"(b));
    return r;
}
__device__ __forceinline__ uint32_t habs2(uint32_t a) { return a & 0x7FFF7FFFu; }

__device__ __forceinline__ void mma16816(float* c, uint32_t a0, uint32_t a1,
                                         uint32_t a2, uint32_t a3,
                                         uint32_t b0, uint32_t b1) {
    asm volatile("mma.sync.aligned.m16n8k16.row.col.f32.bf16.bf16.f32 "
                 "{%0,%1,%2,%3}, {%4,%5,%6,%7}, {%8,%9}, {%0,%1,%2,%3};"
                 : "+f"(c[0]), "+f"(c[1]), "+f"(c[2]), "+f"(c[3])
                 : "r"(a0), "r"(a1), "r"(a2), "r"(a3), "r"(b0), "r"(b1));
}

// ---------------------------------------------------------------------------
// Kernel 1: projections + algebraic fold. Phase A uses f32x2 on row pairs.
// ---------------------------------------------------------------------------
__global__ __launch_bounds__(256) void k1_proj(
    const float* __restrict__ hin, const float* __restrict__ W,
    const float* __restrict__ We1, const float* __restrict__ be1,
    const float* __restrict__ Wa1, const float* __restrict__ ba1)
{
    const int NT = 8;
    int b  = blockIdx.x >> 5;
    int n0 = (blockIdx.x & 31) * NT;
    int tid = threadIdx.x;
    int head = tid >> 6, d = tid & 63;

    __shared__ __align__(16) float hst[FIN*10];   // transposed: hst[f*10+nn]
    __shared__ float whs[NT][FIN];
    __shared__ float eis[NT][FIN];
    __shared__ float ejs[NT][FIN];

    for (int nn = 0; nn < NT; ++nn)
        hst[tid*10 + nn] = hin[((size_t)(b*NN + n0 + nn))*FIN + tid];
    __syncthreads();

    unsigned long long aW[4], aE1[4], aE2[4];
#pragma unroll
    for (int p = 0; p < 4; ++p) { aW[p]=0ull; aE1[p]=0ull; aE2[p]=0ull; }

#pragma unroll 2
    for (int f = 0; f < FIN; ++f) {
        float wv = W  [((size_t)head*FIN + f)*HD + d];
        float w1 = We1[((size_t)head*2*FIN + f)*HD + d];
        float w2 = We1[((size_t)head*2*FIN + FIN + f)*HD + d];
        unsigned long long wv2 = pack2(wv), w12 = pack2(w1), w22 = pack2(w2);
#pragma unroll
        for (int p = 0; p < 4; ++p) {
            unsigned long long hv = *reinterpret_cast<const unsigned long long*>(&hst[f*10 + 2*p]);
            fma2(aW[p],  hv, wv2);
            fma2(aE1[p], hv, w12);
            fma2(aE2[p], hv, w22);
        }
    }

    float accW[NT], accE1[NT], accE2[NT];
#pragma unroll
    for (int p = 0; p < 4; ++p) {
        unpack2(aW[p],  accW[2*p],  accW[2*p+1]);
        unpack2(aE1[p], accE1[2*p], accE1[2*p+1]);
        unpack2(aE2[p], accE2[2*p], accE2[2*p+1]);
    }

    float bei = be1[head*HD + d];
#pragma unroll
    for (int nn = 0; nn < NT; ++nn) {
        size_t base = ((size_t)(b*NH + head)*NN + (n0 + nn))*HD + d;
        float e1 = accE1[nn] + bei;
        g_Wh[base] = accW[nn];
        g_ei[base] = e1;
        g_ej[base] = accE2[nn];
        whs[nn][tid] = accW[nn];
        eis[nn][tid] = e1;
        ejs[nn][tid] = accE2[nn];
    }
    __syncthreads();

    float accSi[NT], accSj[NT], accP[NT], accQ[NT];
#pragma unroll
    for (int nn = 0; nn < NT; ++nn) { accSi[nn]=0.f; accSj[nn]=0.f; accP[nn]=0.f; accQ[nn]=0.f; }

    for (int k0 = 0; k0 < HD; k0 += 4) {
        float wa[4], wb[4], we[4];
#pragma unroll
        for (int t = 0; t < 4; ++t) {
            wa[t] = Wa1[((size_t)head*3*HD +        (k0+t))*HD + d];
            wb[t] = Wa1[((size_t)head*3*HD +   HD + (k0+t))*HD + d];
            we[t] = Wa1[((size_t)head*3*HD + 2*HD + (k0+t))*HD + d];
        }
#pragma unroll
        for (int nn = 0; nn < NT; ++nn) {
            float4 whv = *reinterpret_cast<const float4*>(&whs[nn][head*HD + k0]);
            float4 eiv = *reinterpret_cast<const float4*>(&eis[nn][head*HD + k0]);
            float4 ejv = *reinterpret_cast<const float4*>(&ejs[nn][head*HD + k0]);
            accSi[nn] = fmaf(whv.x, wa[0], accSi[nn]); accSi[nn] = fmaf(whv.y, wa[1], accSi[nn]);
            accSi[nn] = fmaf(whv.z, wa[2], accSi[nn]); accSi[nn] = fmaf(whv.w, wa[3], accSi[nn]);
            accSj[nn] = fmaf(whv.x, wb[0], accSj[nn]); accSj[nn] = fmaf(whv.y, wb[1], accSj[nn]);
            accSj[nn] = fmaf(whv.z, wb[2], accSj[nn]); accSj[nn] = fmaf(whv.w, wb[3], accSj[nn]);
            accP [nn] = fmaf(eiv.x, we[0], accP [nn]); accP [nn] = fmaf(eiv.y, we[1], accP [nn]);
            accP [nn] = fmaf(eiv.z, we[2], accP [nn]); accP [nn] = fmaf(eiv.w, we[3], accP [nn]);
            accQ [nn] = fmaf(ejv.x, we[0], accQ [nn]); accQ [nn] = fmaf(ejv.y, we[1], accQ [nn]);
            accQ [nn] = fmaf(ejv.z, we[2], accQ [nn]); accQ [nn] = fmaf(ejv.w, we[3], accQ [nn]);
        }
    }
    float bsi = ba1[head*HD + d];
#pragma unroll
    for (int nn = 0; nn < NT; ++nn) {
        size_t base = ((size_t)(b*NH + head)*NN + (n0 + nn))*HD + d;
        g_si2[base] = accSi[nn] + bsi + 0.6f*accP[nn];
        g_sj2[base] = accSj[nn]       + 0.6f*accQ[nn];
    }
}

// ---------------------------------------------------------------------------
// t2f: fused edge GEMM (bf16 mma) + masked softmax + hp = attn@Wh + layernorm.
// Block = (b, head, 16 i's), 512 threads = 16 warps (each: 16 j-rows, full d).
// ---------------------------------------------------------------------------
// smem float-offset layout
#define O_EJ   0                       // uint32[256*36]  (bf16x2 ej, pitch 36 words)
#define O_SJ   9216                    // float[256*68]
#define O_WH   26624                   // float[256*68]
#define O_WEB  44032                   // uint32[32*64]   (bf16x2 0.4*We pairs)
#define O_EI   46080                   // uint32[16*32]   (bf16x2 ei)
#define O_SI   46592                   // float[16*64]
#define O_WA2  47616                   // float[64]
#define O_ET   47680                   // float[256*18]   (e then attn; [j][i])
#define O_HP   52288                   // float[16*68]
#define T2_FLOATS 53376
#define T2_BYTES  (T2_FLOATS*4)        // 213504

__global__ __launch_bounds__(512) void t2f(
    const float* __restrict__ Wa1, const float* __restrict__ wa2,
    const int*   __restrict__ adj, const float* __restrict__ ba2,
    const float* __restrict__ ln_g, const float* __restrict__ ln_b)
{
    extern __shared__ __align__(16) float sm[];
    uint32_t* smu = reinterpret_cast<uint32_t*>(sm);

    int bx   = blockIdx.x;
    int it   = bx & 15;
    int head = (bx >> 4) & 3;
    int b    = bx >> 6;
    int i0   = it * 16;
    int tid  = threadIdx.x;
    int wid  = tid >> 5, lane = tid & 31;
    int gid  = lane >> 2, tig = lane & 3;

    size_t bh = (size_t)(b*NH + head);

    // ---- staging ----
    for (int t = tid; t < NN*32; t += 512) {           // EJ -> bf16x2
        int j = t >> 5, kk = t & 31;
        float2 v = *reinterpret_cast<const float2*>(&g_ej[(bh*NN + j)*HD + 2*kk]);
        smu[O_EJ + j*36 + kk] = packbf(v.x, v.y);
    }
    for (int t = tid*4; t < NN*HD; t += 512*4) {       // SJ, WH fp32
        int j = t >> 6, k = t & 63;
        *reinterpret_cast<float4*>(&sm[O_SJ + j*68 + k]) =
            *reinterpret_cast<const float4*>(&g_sj2[(bh*NN + j)*HD + k]);
        *reinterpret_cast<float4*>(&sm[O_WH + j*68 + k]) =
            *reinterpret_cast<const float4*>(&g_Wh[(bh*NN + j)*HD + k]);
    }
    for (int t = tid; t < 32*64; t += 512) {           // WEB: 0.4*We bf16 pairs
        int kk = t >> 6, d = t & 63;
        float f0 = 0.4f * Wa1[((size_t)head*3*HD + 2*HD + 2*kk    )*HD + d];
        float f1 = 0.4f * Wa1[((size_t)head*3*HD + 2*HD + 2*kk + 1)*HD + d];
        smu[O_WEB + t] = packbf(f0, f1);
    }
    for (int t = tid; t < 16*32; t += 512) {           // EI -> bf16x2
        int ii = t >> 5, kk = t & 31;
        float2 v = *reinterpret_cast<const float2*>(&g_ei[(bh*NN + i0 + ii)*HD + 2*kk]);
        smu[O_EI + t] = packbf(v.x, v.y);
    }
    for (int t = tid; t < 16*64; t += 512) {           // SI fp32
        int ii = t >> 6, d = t & 63;
        sm[O_SI + t] = g_si2[(bh*NN + i0 + ii)*HD + d];
    }
    if (tid < 64) sm[O_WA2 + tid] = wa2[head*HD + tid];
    __syncthreads();

    // ---- resident B fragments ----
    uint32_t bfr[4][8][2];
#pragma unroll
    for (int ks = 0; ks < 4; ++ks)
#pragma unroll
        for (int nt = 0; nt < 8; ++nt) {
            int d = nt*8 + gid;
            bfr[ks][nt][0] = smu[O_WEB + (ks*8 + tig    )*64 + d];
            bfr[ks][nt][1] = smu[O_WEB + (ks*8 + tig + 4)*64 + d];
        }

    // ---- edge phase: warp owns j rows [wid*16, wid*16+16) ----
    int j0 = wid*16;
    int r0 = j0 + gid, r1 = r0 + 8;

    for (int ii = 0; ii < 16; ++ii) {
        uint32_t eir[8];
#pragma unroll
        for (int ks = 0; ks < 4; ++ks) {
            eir[2*ks]   = smu[O_EI + ii*32 + ks*8 + tig];
            eir[2*ks+1] = smu[O_EI + ii*32 + ks*8 + 4 + tig];
        }
        float acc[8][4];
#pragma unroll
        for (int nt = 0; nt < 8; ++nt) {
            float2 s = *reinterpret_cast<const float2*>(&sm[O_SI + ii*64 + nt*8 + 2*tig]);
            acc[nt][0] = s.x; acc[nt][1] = s.y; acc[nt][2] = s.x; acc[nt][3] = s.y;
        }
#pragma unroll
        for (int ks = 0; ks < 4; ++ks) {
            uint32_t e0 = smu[O_EJ + r0*36 + ks*8 + tig];
            uint32_t e1 = smu[O_EJ + r1*36 + ks*8 + tig];
            uint32_t e2 = smu[O_EJ + r0*36 + ks*8 + 4 + tig];
            uint32_t e3 = smu[O_EJ + r1*36 + ks*8 + 4 + tig];
            uint32_t a0 = habs2(hadd2(e0, eir[2*ks]));
            uint32_t a1 = habs2(hadd2(e1, eir[2*ks]));
            uint32_t a2 = habs2(hadd2(e2, eir[2*ks+1]));
            uint32_t a3 = habs2(hadd2(e3, eir[2*ks+1]));
#pragma unroll
            for (int nt = 0; nt < 8; ++nt)
                mma16816(acc[nt], a0, a1, a2, a3, bfr[ks][nt][0], bfr[ks][nt][1]);
        }
        // epilogue: e[i, r0], e[i, r1]
        float pe0 = 0.f, pe1 = 0.f;
#pragma unroll
        for (int nt = 0; nt < 8; ++nt) {
            int d = nt*8 + 2*tig;
            float2 sj0 = *reinterpret_cast<const float2*>(&sm[O_SJ + r0*68 + d]);
            float2 sj1 = *reinterpret_cast<const float2*>(&sm[O_SJ + r1*68 + d]);
            float2 w2  = *reinterpret_cast<const float2*>(&sm[O_WA2 + d]);
            float v00 = acc[nt][0] + sj0.x, v01 = acc[nt][1] + sj0.y;
            float v10 = acc[nt][2] + sj1.x, v11 = acc[nt][3] + sj1.y;
            pe0 = fmaf(fmaxf(v00, ALPHA*v00), w2.x, pe0);
            pe0 = fmaf(fmaxf(v01, ALPHA*v01), w2.y, pe0);
            pe1 = fmaf(fmaxf(v10, ALPHA*v10), w2.x, pe1);
            pe1 = fmaf(fmaxf(v11, ALPHA*v11), w2.y, pe1);
        }
        pe0 += __shfl_xor_sync(0xffffffffu, pe0, 1);
        pe0 += __shfl_xor_sync(0xffffffffu, pe0, 2);
        pe1 += __shfl_xor_sync(0xffffffffu, pe1, 1);
        pe1 += __shfl_xor_sync(0xffffffffu, pe1, 2);
        if (tig == 0) {
            sm[O_ET + r0*18 + ii] = pe0;
            sm[O_ET + r1*18 + ii] = pe1;
        }
    }
    __syncthreads();

    // ---- masked softmax: warp wid handles i = wid ----
    {
        int i = wid;
        int iglob = i0 + i;
        float bav = ba2[head];
        float vals[8]; float mx = -1e30f;
#pragma unroll
        for (int s = 0; s < 8; ++s) {
            int j = lane + 32*s;
            float pe = sm[O_ET + j*18 + i] + bav;
            int a = adj[((size_t)b*NN + iglob)*NN + j];
            vals[s] = (a == 0) ? -1e9f : pe;
            mx = fmaxf(mx, vals[s]);
        }
#pragma unroll
        for (int o = 16; o; o >>= 1) mx = fmaxf(mx, __shfl_xor_sync(0xffffffffu, mx, o));
        float se = 0.f;
#pragma unroll
        for (int s = 0; s < 8; ++s) { vals[s] = __expf(vals[s] - mx); se += vals[s]; }
#pragma unroll
        for (int o = 16; o; o >>= 1) se += __shfl_xor_sync(0xffffffffu, se, o);
        float inv = 1.0f / se;
#pragma unroll
        for (int s = 0; s < 8; ++s)
            sm[O_ET + (lane + 32*s)*18 + i] = vals[s] * inv;
    }
    __syncthreads();

    // ---- hp[i][d] = sum_j attn[i][j] * Wh[j][d]   (f32x2 over i-pairs) ----
    {
        int d = tid & 63, ig = tid >> 6;          // ig 0..7 -> i pair {2ig, 2ig+1}
        unsigned long long acc2 = 0ull;
#pragma unroll 4
        for (int j = 0; j < NN; ++j) {
            float wh = sm[O_WH + j*68 + d];
            unsigned long long at = *reinterpret_cast<const unsigned long long*>(&sm[O_ET + j*18 + 2*ig]);
            fma2(acc2, at, pack2(wh));
        }
        float h0, h1; unpack2(acc2, h0, h1);
        sm[O_HP + (2*ig    )*68 + d] = h0;
        sm[O_HP + (2*ig + 1)*68 + d] = h1;
    }
    __syncthreads();

    // ---- per-head layernorm: warp wid handles i = wid ----
    {
        int i = wid;
        float x0 = sm[O_HP + i*68 + lane];
        float x1 = sm[O_HP + i*68 + 32 + lane];
        float s1 = x0 + x1, s2 = x0*x0 + x1*x1;
#pragma unroll
        for (int o = 16; o; o >>= 1) {
            s1 += __shfl_xor_sync(0xffffffffu, s1, o);
            s2 += __shfl_xor_sync(0xffffffffu, s2, o);
        }
        float m   = s1 * (1.0f/64.0f);
        float var = s2 * (1.0f/64.0f) - m*m;
        float r   = rsqrtf(var + 1e-5f);
        size_t obase = ((size_t)(b*NN) + i0 + i)*FIN + head*HD;
        g_concat[obase + lane]      = (x0 - m)*r*ln_g[head*HD + lane]      + ln_b[head*HD + lane];
        g_concat[obase + 32 + lane] = (x1 - m)*r*ln_g[head*HD + 32 + lane] + ln_b[head*HD + 32 + lane];
    }
}

// ---------------------------------------------------------------------------
// Kernel 3: out = layernorm(concat @ Wo + bo + h).  f32x2 on row pairs.
// ---------------------------------------------------------------------------
__global__ __launch_bounds__(256) void k3_out(
    const float* __restrict__ hin, const float* __restrict__ Wo,
    const float* __restrict__ bo,  const float* __restrict__ g2,
    const float* __restrict__ b2,  float* __restrict__ out)
{
    const int NT = 8;
    int b  = blockIdx.x / (NN / NT);
    int n0 = (blockIdx.x % (NN / NT)) * NT;
    int tid = threadIdx.x;

    __shared__ __align__(16) float cst[FIN*10];   // transposed: cst[f*10+nn]
    __shared__ float hs2[NT][FIN];

    for (int nn = 0; nn < NT; ++nn) {
        cst[tid*10 + nn] = g_concat[((size_t)b*NN + n0 + nn)*FIN + tid];
        hs2[nn][tid]     = hin     [((size_t)b*NN + n0 + nn)*FIN + tid];
    }
    __syncthreads();

    float bv = bo[tid];
    unsigned long long a2[4];
#pragma unroll
    for (int p = 0; p < 4; ++p) a2[p] = pack2(bv);

#pragma unroll 4
    for (int f = 0; f < FIN; ++f) {
        unsigned long long w2 = pack2(Wo[(size_t)f*FIN + tid]);
#pragma unroll
        for (int p = 0; p < 4; ++p) {
            unsigned long long cv = *reinterpret_cast<const unsigned long long*>(&cst[f*10 + 2*p]);
            fma2(a2[p], cv, w2);
        }
    }
    float acc[NT];
#pragma unroll
    for (int p = 0; p < 4; ++p) unpack2(a2[p], acc[2*p], acc[2*p+1]);

    __syncthreads();
    for (int nn = 0; nn < NT; ++nn)
        hs2[nn][tid] = acc[nn] + hs2[nn][tid];
    __syncthreads();

    int wr = tid >> 5, lane = tid & 31;
    float s1 = 0.f, s2 = 0.f;
    for (int o = lane; o < FIN; o += 32) {
        float x = hs2[wr][o]; s1 += x; s2 += x*x;
    }
#pragma unroll
    for (int o = 16; o; o >>= 1) {
        s1 += __shfl_xor_sync(0xffffffffu, s1, o);
        s2 += __shfl_xor_sync(0xffffffffu, s2, o);
    }
    float m   = s1 * (1.0f/256.0f);
    float var = s2 * (1.0f/256.0f) - m*m;
    float r   = rsqrtf(var + 1e-5f);
    for (int o = lane; o < FIN; o += 32) {
        float x = hs2[wr][o];
        out[((size_t)b*NN + n0 + wr)*FIN + o] = (x - m) * r * g2[o] + b2[o];
    }
}

// ---------------------------------------------------------------------------
extern "C" void kernel_launch(void* const* d_in, const int* in_sizes, int n_in,
                              void* d_out, int out_size)
{
    const float* h    = (const float*)d_in[0];
    const int*   adj  = (const int*)  d_in[1];
    const float* W    = (const float*)d_in[2];
    const float* We1  = (const float*)d_in[3];
    const float* be1  = (const float*)d_in[4];
    const float* Wa1  = (const float*)d_in[5];
    const float* ba1  = (const float*)d_in[6];
    const float* wa2  = (const float*)d_in[7];
    const float* ba2  = (const float*)d_in[8];
    const float* ln_g = (const float*)d_in[9];
    const float* ln_b = (const float*)d_in[10];
    const float* Wo   = (const float*)d_in[11];
    const float* bo   = (const float*)d_in[12];
    const float* g2   = (const float*)d_in[13];
    const float* b2   = (const float*)d_in[14];
    float* out = (float*)d_out;

    cudaFuncSetAttribute(t2f, cudaFuncAttributeMaxDynamicSharedMemorySize, T2_BYTES);

    k1_proj<<<NB*(NN/8), 256>>>(h, W, We1, be1, Wa1, ba1);
    t2f    <<<NB*NH*(NN/16), 512, T2_BYTES>>>(Wa1, wa2, adj, ba2, ln_g, ln_b);
    k3_out <<<NB*(NN/8), 256>>>(h, Wo, bo, g2, b2, out);
}